// round 7
// baseline (speedup 1.0000x reference)
#include <cuda_runtime.h>
#include <cuda_bf16.h>
#include <cuda_fp16.h>
#include <cstdint>

#define NN_CAP 100000
#define EE_CAP 1600000
#define SCAN_B 1024

// ---------------- scratch (device globals) ----------------
__device__ int    g_is64;
__device__ int    g_cnt[NN_CAP];
__device__ int    g_off[NN_CAP + 1];
__device__ int    g_cur[NN_CAP];
__device__ int    g_bsum[(NN_CAP + SCAN_B - 1) / SCAN_B];
__device__ int    g_bpre[(NN_CAP + SCAN_B - 1) / SCAN_B];
__device__ int    g_ssrc[EE_CAP];
__device__ __half g_xl1h[(size_t)NN_CAP * 128];   // fp16 gather payload, layer 1
__device__ float  g_xr1[(size_t)NN_CAP * 128];
__device__ float  g_h  [(size_t)NN_CAP * 128];
__device__ __half g_xl2h[(size_t)NN_CAP * 64];    // fp16 gather payload, layer 2
__device__ float  g_xr2[(size_t)NN_CAP * 64];
// split weights, [NOUT][K=128] bf16 (transposed, K-major rows)
__device__ __nv_bfloat16 g_w1lh[16384], g_w1ll[16384], g_w1rh[16384], g_w1rl[16384];
__device__ __nv_bfloat16 g_w2lh[8192],  g_w2ll[8192],  g_w2rh[8192],  g_w2rl[8192];

// ---------------- helpers ----------------
__device__ __forceinline__ uint32_t smem_u32(const void* p) {
    uint32_t a;
    asm("{ .reg .u64 t; cvta.to.shared.u64 t, %1; cvt.u32.u64 %0, t; }" : "=r"(a) : "l"(p));
    return a;
}
__device__ __forceinline__ void ldsm_x4(uint32_t& r0, uint32_t& r1, uint32_t& r2, uint32_t& r3,
                                        uint32_t addr) {
    asm volatile("ldmatrix.sync.aligned.m8n8.x4.shared.b16 {%0,%1,%2,%3}, [%4];"
                 : "=r"(r0), "=r"(r1), "=r"(r2), "=r"(r3) : "r"(addr));
}
__device__ __forceinline__ void mma16816(float* c, const uint32_t* a, const uint32_t* b) {
    asm volatile(
        "mma.sync.aligned.m16n8k16.row.col.f32.bf16.bf16.f32 "
        "{%0,%1,%2,%3}, {%4,%5,%6,%7}, {%8,%9}, {%0,%1,%2,%3};"
        : "+f"(c[0]), "+f"(c[1]), "+f"(c[2]), "+f"(c[3])
        : "r"(a[0]), "r"(a[1]), "r"(a[2]), "r"(a[3]), "r"(b[0]), "r"(b[1]));
}
__device__ __forceinline__ uint32_t pack2(float a, float b) {
    __nv_bfloat162 t = __floats2bfloat162_rn(a, b);
    return *(uint32_t*)&t;
}
__device__ __forceinline__ float4 h4_to_f4(uint2 u) {
    float2 a = __half22float2(*(__half2*)&u.x);
    float2 b = __half22float2(*(__half2*)&u.y);
    return make_float4(a.x, a.y, b.x, b.y);
}
__device__ __forceinline__ float lrelu(float v) { return v > 0.f ? v : 0.2f * v; }
__device__ __forceinline__ int edge_dst(const int* __restrict__ ei, int e, int E, int is64) {
    return is64 ? ei[2 * (E + e)] : ei[E + e];
}
__device__ __forceinline__ int edge_src(const int* __restrict__ ei, int e, int E, int is64) {
    return is64 ? ei[2 * e] : ei[e];
}

// ---------------- dtype detection ----------------
__global__ void k_detect(const int* __restrict__ ei, int E) {
    __shared__ int nz;
    if (threadIdx.x == 0) nz = 0;
    __syncthreads();
    int cnt = E < 4096 ? E : 4096;
    for (int i = threadIdx.x; i < cnt; i += blockDim.x)
        if (ei[2 * i + 1] != 0) nz = 1;
    __syncthreads();
    if (threadIdx.x == 0) g_is64 = (nz == 0) ? 1 : 0;
}

// ---------------- CSR build ----------------
__global__ void k_zero_cnt(int N) {
    int t = blockIdx.x * blockDim.x + threadIdx.x;
    if (t < N) g_cnt[t] = 0;
}
__global__ void k_hist(const int* __restrict__ ei, int E) {
    int e = blockIdx.x * blockDim.x + threadIdx.x;
    if (e >= E) return;
    atomicAdd(&g_cnt[edge_dst(ei, e, E, g_is64)], 1);
}
__global__ void k_scan1(int N) {
    __shared__ int wsum[32];
    const int tid = threadIdx.x;
    const int i = blockIdx.x * SCAN_B + tid;
    const int lane = tid & 31, wid = tid >> 5;
    int v = (i < N) ? g_cnt[i] : 0;
    int incl = v;
#pragma unroll
    for (int o = 1; o < 32; o <<= 1) {
        int t = __shfl_up_sync(0xFFFFFFFFu, incl, o);
        if (lane >= o) incl += t;
    }
    if (lane == 31) wsum[wid] = incl;
    __syncthreads();
    if (wid == 0) {
        int w = wsum[lane];
        int wi = w;
#pragma unroll
        for (int o = 1; o < 32; o <<= 1) {
            int t = __shfl_up_sync(0xFFFFFFFFu, wi, o);
            if (lane >= o) wi += t;
        }
        wsum[lane] = wi - w;
        if (lane == 31) g_bsum[blockIdx.x] = wi;
    }
    __syncthreads();
    if (i < N) g_off[i] = incl - v + wsum[wid];
}
__global__ void k_scan2(int NB, int N) {
    const int lane = threadIdx.x & 31, wid = threadIdx.x >> 5;
    __shared__ int wsum[4];
    int v = (threadIdx.x < NB) ? g_bsum[threadIdx.x] : 0;
    int incl = v;
#pragma unroll
    for (int o = 1; o < 32; o <<= 1) {
        int t = __shfl_up_sync(0xFFFFFFFFu, incl, o);
        if (lane >= o) incl += t;
    }
    if (lane == 31) wsum[wid] = incl;
    __syncthreads();
    int pre = 0;
    for (int w = 0; w < wid; w++) pre += wsum[w];
    if (threadIdx.x < NB) g_bpre[threadIdx.x] = pre + incl - v;
    if (threadIdx.x == 127) g_off[N] = pre + incl;
}
__global__ void k_scan3(int N) {
    int t = blockIdx.x * blockDim.x + threadIdx.x;
    if (t >= N) return;
    int o = g_off[t] + g_bpre[t >> 10];
    g_off[t] = o;
    g_cur[t] = o;
}
__global__ void k_scatter(const int* __restrict__ ei, int E) {
    int e = blockIdx.x * blockDim.x + threadIdx.x;
    if (e >= E) return;
    int is64 = g_is64;
    int s = edge_src(ei, e, E, is64), d = edge_dst(ei, e, E, is64);
    int pos = atomicAdd(&g_cur[d], 1);
    g_ssrc[pos] = s;
}

// ---------------- weight prep: transpose + bf16 split ----------------
__global__ void k_wprep(const float* __restrict__ W1l, const float* __restrict__ W1r,
                        const float* __restrict__ W2l, const float* __restrict__ W2r) {
    int t = blockIdx.x * blockDim.x + threadIdx.x;
    const float* W; __nv_bfloat16 *oh, *ol; int NOUT, idx;
    if      (t < 16384)  { W = W1l; oh = g_w1lh; ol = g_w1ll; NOUT = 128; idx = t; }
    else if (t < 32768)  { W = W1r; oh = g_w1rh; ol = g_w1rl; NOUT = 128; idx = t - 16384; }
    else if (t < 40960)  { W = W2l; oh = g_w2lh; ol = g_w2ll; NOUT = 64;  idx = t - 32768; }
    else if (t < 49152)  { W = W2r; oh = g_w2rh; ol = g_w2rl; NOUT = 64;  idx = t - 40960; }
    else return;
    int n = idx >> 7, k = idx & 127;
    float v = W[k * NOUT + n];
    __nv_bfloat16 h = __float2bfloat16_rn(v);
    oh[idx] = h;
    ol[idx] = __float2bfloat16_rn(v - __bfloat162float(h));
}

// ---------------- mma.sync GEMM pair: Yl(h fp16) = X@Wl + bl, Yr(fp32) = X@Wr + br ----
template <int NOUT>
__global__ void __launch_bounds__(256, 1) k_gemm_mma(
    const float* __restrict__ X,
    const __nv_bfloat16* __restrict__ Wlh, const __nv_bfloat16* __restrict__ Wll,
    const __nv_bfloat16* __restrict__ Wrh, const __nv_bfloat16* __restrict__ Wrl,
    const float* __restrict__ bl, const float* __restrict__ br,
    __half* __restrict__ Ylh, float* __restrict__ Yr, int nrows)
{
    constexpr int PITCH = 136;
    constexpr int ABYTES = 128 * PITCH * 2;
    constexpr int BBYTES = NOUT * PITCH * 2;
    constexpr int NFRAG = NOUT / 16;
    constexpr int WN = NOUT / 2;

    extern __shared__ char sm[];
    __nv_bfloat16* Ah = (__nv_bfloat16*)sm;
    __nv_bfloat16* Al = (__nv_bfloat16*)(sm + ABYTES);
    __nv_bfloat16* Bt = (__nv_bfloat16*)(sm + 2 * ABYTES);

    const int tid = threadIdx.x, wid = tid >> 5, lane = tid & 31;
    const int wm = wid & 3, wn = wid >> 2;
    const int base = blockIdx.x * 128;

    for (int c = tid; c < 2048; c += 256) {
        int row = c >> 4, col8 = (c & 15) << 3;
        int gr = base + row;
        float4 v0 = make_float4(0.f, 0.f, 0.f, 0.f), v1 = v0;
        if (gr < nrows) {
            v0 = *(const float4*)&X[(size_t)gr * 128 + col8];
            v1 = *(const float4*)&X[(size_t)gr * 128 + col8 + 4];
        }
        float in[8] = {v0.x, v0.y, v0.z, v0.w, v1.x, v1.y, v1.z, v1.w};
        float hf[8], lf[8];
#pragma unroll
        for (int i = 0; i < 8; i++) {
            __nv_bfloat16 hb = __float2bfloat16_rn(in[i]);
            hf[i] = __bfloat162float(hb);
            lf[i] = in[i] - hf[i];
        }
        uint4 hh = make_uint4(pack2(hf[0], hf[1]), pack2(hf[2], hf[3]),
                              pack2(hf[4], hf[5]), pack2(hf[6], hf[7]));
        uint4 ll = make_uint4(pack2(lf[0], lf[1]), pack2(lf[2], lf[3]),
                              pack2(lf[4], lf[5]), pack2(lf[6], lf[7]));
        *(uint4*)&Ah[row * PITCH + col8] = hh;
        *(uint4*)&Al[row * PITCH + col8] = ll;
    }
    const __nv_bfloat16* wsrc[4] = {Wlh, Wll, Wrh, Wrl};
#pragma unroll
    for (int w = 0; w < 4; w++) {
        __nv_bfloat16* dst = Bt + w * (NOUT * PITCH);
        const __nv_bfloat16* src = wsrc[w];
        for (int c = tid; c < NOUT * 16; c += 256) {
            int row = c >> 4, col8 = (c & 15) << 3;
            *(uint4*)&dst[row * PITCH + col8] = *(const uint4*)&src[row * 128 + col8];
        }
    }
    __syncthreads();

    const int quad = lane >> 3, r = lane & 7;
    const int a_row_off = (quad & 1) * 8 + r, a_col_off = (quad >> 1) * 8;
    const int b_row_off = (quad >> 1) * 8 + r, b_col_off = (quad & 1) * 8;

    const uint32_t ah_u = smem_u32(Ah), al_u = smem_u32(Al), b_u = smem_u32(Bt);

#pragma unroll
    for (int out = 0; out < 2; out++) {
        float acc[2][NFRAG][4];
#pragma unroll
        for (int mf = 0; mf < 2; mf++)
#pragma unroll
            for (int nf = 0; nf < NFRAG; nf++)
                acc[mf][nf][0] = acc[mf][nf][1] = acc[mf][nf][2] = acc[mf][nf][3] = 0.f;

#pragma unroll
        for (int p = 0; p < 3; p++) {
            uint32_t a_base = (p == 2) ? al_u : ah_u;
            uint32_t b_base = b_u + (uint32_t)(out * 2 + (p == 1)) * BBYTES;
#pragma unroll
            for (int ks = 0; ks < 8; ks++) {
                uint32_t af[2][4];
#pragma unroll
                for (int mf = 0; mf < 2; mf++) {
                    uint32_t ad = a_base +
                        ((wm * 32 + mf * 16 + a_row_off) * PITCH + ks * 16 + a_col_off) * 2;
                    ldsm_x4(af[mf][0], af[mf][1], af[mf][2], af[mf][3], ad);
                }
                uint32_t bfr[NFRAG][2];
#pragma unroll
                for (int nfp = 0; nfp < NFRAG / 2; nfp++) {
                    uint32_t bd = b_base +
                        ((wn * WN + nfp * 16 + b_row_off) * PITCH + ks * 16 + b_col_off) * 2;
                    uint32_t d0, d1, d2, d3;
                    ldsm_x4(d0, d1, d2, d3, bd);
                    bfr[2 * nfp][0] = d0; bfr[2 * nfp][1] = d1;
                    bfr[2 * nfp + 1][0] = d2; bfr[2 * nfp + 1][1] = d3;
                }
#pragma unroll
                for (int mf = 0; mf < 2; mf++)
#pragma unroll
                    for (int nf = 0; nf < NFRAG; nf++)
                        mma16816(acc[mf][nf], af[mf], bfr[nf]);
            }
        }

        const float* bias = out ? br : bl;
#pragma unroll
        for (int mf = 0; mf < 2; mf++) {
            int row0 = base + wm * 32 + mf * 16 + (lane >> 2);
#pragma unroll
            for (int nf = 0; nf < NFRAG; nf++) {
                int col = wn * WN + nf * 8 + (lane & 3) * 2;
                float b0 = __ldg(&bias[col]), b1 = __ldg(&bias[col + 1]);
                if (out == 0) {   // xl path -> fp16
                    if (row0 < nrows)
                        *(__half2*)&Ylh[(size_t)row0 * NOUT + col] =
                            __floats2half2_rn(acc[mf][nf][0] + b0, acc[mf][nf][1] + b1);
                    if (row0 + 8 < nrows)
                        *(__half2*)&Ylh[(size_t)(row0 + 8) * NOUT + col] =
                            __floats2half2_rn(acc[mf][nf][2] + b0, acc[mf][nf][3] + b1);
                } else {          // xr path -> fp32
                    if (row0 < nrows)
                        *(float2*)&Yr[(size_t)row0 * NOUT + col] =
                            make_float2(acc[mf][nf][0] + b0, acc[mf][nf][1] + b1);
                    if (row0 + 8 < nrows)
                        *(float2*)&Yr[(size_t)(row0 + 8) * NOUT + col] =
                            make_float2(acc[mf][nf][2] + b0, acc[mf][nf][3] + b1);
                }
            }
        }
    }
}

// ---------------- layer 1 fused attention (fp16 gathers, depth-2 pipeline) ----------------
__global__ void k_attn1(const float* __restrict__ att, const float* __restrict__ bias, int N) {
    int node = blockIdx.x * 8 + (threadIdx.x >> 5);
    int lane = threadIdx.x & 31;
    if (node >= N) return;
    const int d = node;
    const __half* XL = g_xl1h;

    float4 xr = *(const float4*)&g_xr1[(size_t)d * 128 + lane * 4];
    float4 at = *(const float4*)&att[lane * 4];

    float4 self = h4_to_f4(*(const uint2*)&XL[(size_t)d * 128 + lane * 4]);
    float sc = lrelu(self.x + xr.x) * at.x + lrelu(self.y + xr.y) * at.y +
               lrelu(self.z + xr.z) * at.z + lrelu(self.w + xr.w) * at.w;
    sc += __shfl_xor_sync(0xFFFFFFFFu, sc, 1);
    sc += __shfl_xor_sync(0xFFFFFFFFu, sc, 2);
    float m = sc, den = 1.f;
    float4 acc = self;

    const int beg = g_off[d];
    const int cnt = g_off[d + 1] - beg;
    uint2 v0, v1;
    if (cnt > 0) {
        int s0 = __ldg(&g_ssrc[beg]);
        v0 = *(const uint2*)&XL[(size_t)s0 * 128 + lane * 4];
    }
    if (cnt > 1) {
        int s1 = __ldg(&g_ssrc[beg + 1]);
        v1 = *(const uint2*)&XL[(size_t)s1 * 128 + lane * 4];
    }
    for (int j = 0; j < cnt; j++) {
        uint2 raw = v0;
        v0 = v1;
        if (j + 2 < cnt) {
            int sn = __ldg(&g_ssrc[beg + j + 2]);
            v1 = *(const uint2*)&XL[(size_t)sn * 128 + lane * 4];
        }
        float4 cur = h4_to_f4(raw);
        sc = lrelu(cur.x + xr.x) * at.x + lrelu(cur.y + xr.y) * at.y +
             lrelu(cur.z + xr.z) * at.z + lrelu(cur.w + xr.w) * at.w;
        sc += __shfl_xor_sync(0xFFFFFFFFu, sc, 1);
        sc += __shfl_xor_sync(0xFFFFFFFFu, sc, 2);
        float nm = fmaxf(m, sc);
        float cold = __expf(m - nm), wgt = __expf(sc - nm);
        den = den * cold + wgt;
        acc.x = acc.x * cold + wgt * cur.x;
        acc.y = acc.y * cold + wgt * cur.y;
        acc.z = acc.z * cold + wgt * cur.z;
        acc.w = acc.w * cold + wgt * cur.w;
        m = nm;
    }
    float inv = 1.f / den;
    float4 bi = *(const float4*)&bias[lane * 4];
    float4 o;
    o.x = acc.x * inv + bi.x; o.y = acc.y * inv + bi.y;
    o.z = acc.z * inv + bi.z; o.w = acc.w * inv + bi.w;
    o.x = o.x > 0.f ? o.x : expm1f(o.x);
    o.y = o.y > 0.f ? o.y : expm1f(o.y);
    o.z = o.z > 0.f ? o.z : expm1f(o.z);
    o.w = o.w > 0.f ? o.w : expm1f(o.w);
    *(float4*)&g_h[(size_t)d * 128 + lane * 4] = o;
}

// ---------------- layer 2 fused attention (lane owns channels 2l, 2l+1) ----------------
__global__ void k_attn2(const float* __restrict__ att2, const float* __restrict__ bias2,
                        float* __restrict__ dout, int N) {
    int node = blockIdx.x * 8 + (threadIdx.x >> 5);
    int lane = threadIdx.x & 31;
    if (node >= N) return;
    const int d = node;
    const __half* XL = g_xl2h;

    float2 xr = *(const float2*)&g_xr2[(size_t)d * 64 + lane * 2];
    float2 at = *(const float2*)&att2[lane * 2];

    float2 self = __half22float2(*(const __half2*)&XL[(size_t)d * 64 + lane * 2]);
    float sc = lrelu(self.x + xr.x) * at.x + lrelu(self.y + xr.y) * at.y;
#pragma unroll
    for (int o = 16; o; o >>= 1) sc += __shfl_xor_sync(0xFFFFFFFFu, sc, o);
    float m = sc, den = 1.f;
    float acc0 = self.x, acc1 = self.y;

    const int beg = g_off[d];
    const int cnt = g_off[d + 1] - beg;
    uint32_t v0, v1;
    if (cnt > 0) {
        int s0 = __ldg(&g_ssrc[beg]);
        v0 = *(const uint32_t*)&XL[(size_t)s0 * 64 + lane * 2];
    }
    if (cnt > 1) {
        int s1 = __ldg(&g_ssrc[beg + 1]);
        v1 = *(const uint32_t*)&XL[(size_t)s1 * 64 + lane * 2];
    }
    for (int j = 0; j < cnt; j++) {
        uint32_t raw = v0;
        v0 = v1;
        if (j + 2 < cnt) {
            int sn = __ldg(&g_ssrc[beg + j + 2]);
            v1 = *(const uint32_t*)&XL[(size_t)sn * 64 + lane * 2];
        }
        float2 cur = __half22float2(*(__half2*)&raw);
        sc = lrelu(cur.x + xr.x) * at.x + lrelu(cur.y + xr.y) * at.y;
#pragma unroll
        for (int o = 16; o; o >>= 1) sc += __shfl_xor_sync(0xFFFFFFFFu, sc, o);
        float nm = fmaxf(m, sc);
        float cold = __expf(m - nm), wgt = __expf(sc - nm);
        den = den * cold + wgt;
        acc0 = acc0 * cold + wgt * cur.x;
        acc1 = acc1 * cold + wgt * cur.y;
        m = nm;
    }
    float inv = 1.f / den;
    float2 bi = *(const float2*)&bias2[lane * 2];
    *(float2*)&dout[(size_t)d * 64 + lane * 2] =
        make_float2(acc0 * inv + bi.x, acc1 * inv + bi.y);
}

// ---------------- launch ----------------
static inline int cdiv(long long a, int b) { return (int)((a + b - 1) / b); }

extern "C" void kernel_launch(void* const* d_in, const int* in_sizes, int n_in,
                              void* d_out, int out_size) {
    const float* x    = (const float*)d_in[0];
    const int*   ei   = (const int*)d_in[1];
    const float* Wl1  = (const float*)d_in[2];
    const float* bl1  = (const float*)d_in[3];
    const float* Wr1  = (const float*)d_in[4];
    const float* br1  = (const float*)d_in[5];
    const float* att1 = (const float*)d_in[6];
    const float* bias1= (const float*)d_in[7];
    const float* Wl2  = (const float*)d_in[8];
    const float* bl2  = (const float*)d_in[9];
    const float* Wr2  = (const float*)d_in[10];
    const float* br2  = (const float*)d_in[11];
    const float* att2 = (const float*)d_in[12];
    const float* bias2= (const float*)d_in[13];
    float* dout = (float*)d_out;

    const int N = in_sizes[0] / 128;
    const int E = in_sizes[1] / 2;
    const int NB = cdiv(N, SCAN_B);

    float *xr1, *h, *xr2;
    __half *xl1h, *xl2h;
    cudaGetSymbolAddress((void**)&xl1h, g_xl1h);
    cudaGetSymbolAddress((void**)&xr1,  g_xr1);
    cudaGetSymbolAddress((void**)&h,    g_h);
    cudaGetSymbolAddress((void**)&xl2h, g_xl2h);
    cudaGetSymbolAddress((void**)&xr2,  g_xr2);
    __nv_bfloat16 *w1lh, *w1ll, *w1rh, *w1rl, *w2lh, *w2ll, *w2rh, *w2rl;
    cudaGetSymbolAddress((void**)&w1lh, g_w1lh);
    cudaGetSymbolAddress((void**)&w1ll, g_w1ll);
    cudaGetSymbolAddress((void**)&w1rh, g_w1rh);
    cudaGetSymbolAddress((void**)&w1rl, g_w1rl);
    cudaGetSymbolAddress((void**)&w2lh, g_w2lh);
    cudaGetSymbolAddress((void**)&w2ll, g_w2ll);
    cudaGetSymbolAddress((void**)&w2rh, g_w2rh);
    cudaGetSymbolAddress((void**)&w2rl, g_w2rl);

    const int smem1 = 2 * 34816 + 4 * 34816;   // 208896 (NOUT=128)
    const int smem2 = 2 * 34816 + 4 * 17408;   // 139264 (NOUT=64)
    cudaFuncSetAttribute(k_gemm_mma<128>, cudaFuncAttributeMaxDynamicSharedMemorySize, smem1);
    cudaFuncSetAttribute(k_gemm_mma<64>,  cudaFuncAttributeMaxDynamicSharedMemorySize, smem2);

    // dtype + CSR build
    k_detect  <<<1, 256>>>(ei, E);
    k_zero_cnt<<<cdiv(N, 256), 256>>>(N);
    k_hist    <<<cdiv(E, 256), 256>>>(ei, E);
    k_scan1   <<<NB, SCAN_B>>>(N);
    k_scan2   <<<1, 128>>>(NB, N);
    k_scan3   <<<cdiv(N, 256), 256>>>(N);
    k_scatter <<<cdiv(E, 256), 256>>>(ei, E);

    // weight prep (bf16 split + transpose)
    k_wprep<<<cdiv(49152, 256), 256>>>(Wl1, Wr1, Wl2, Wr2);

    // layer 1
    k_gemm_mma<128><<<cdiv(N, 128), 256, smem1>>>(x, w1lh, w1ll, w1rh, w1rl,
                                                  bl1, br1, xl1h, xr1, N);
    k_attn1<<<cdiv(N, 8), 256>>>(att1, bias1, N);

    // layer 2
    k_gemm_mma<64><<<cdiv(N, 128), 256, smem2>>>(h, w2lh, w2ll, w2rh, w2rl,
                                                 bl2, br2, xl2h, xr2, N);
    k_attn2<<<cdiv(N, 8), 256>>>(att2, bias2, dout, N);
}

// round 8
// speedup vs baseline: 1.1322x; 1.1322x over previous
#include <cuda_runtime.h>
#include <cuda_bf16.h>
#include <cuda_fp16.h>
#include <cstdint>

#define NN_CAP 100000
#define EE_CAP 1600000
#define SCAN_B 1024

// ---------------- scratch (device globals) ----------------
__device__ int    g_is64;
__device__ int    g_cnt[NN_CAP];
__device__ int    g_off[NN_CAP + 1];
__device__ int    g_cur[NN_CAP];
__device__ int    g_bsum[(NN_CAP + SCAN_B - 1) / SCAN_B];
__device__ int    g_bpre[(NN_CAP + SCAN_B - 1) / SCAN_B];
__device__ int    g_ssrc[EE_CAP];
__device__ __half g_xl1h[(size_t)NN_CAP * 128];
__device__ float  g_xr1[(size_t)NN_CAP * 128];
__device__ float  g_h  [(size_t)NN_CAP * 128];
__device__ __half g_xl2h[(size_t)NN_CAP * 64];
__device__ float  g_xr2[(size_t)NN_CAP * 64];
__device__ __nv_bfloat16 g_w1lh[16384], g_w1ll[16384], g_w1rh[16384], g_w1rl[16384];
__device__ __nv_bfloat16 g_w2lh[8192],  g_w2ll[8192],  g_w2rh[8192],  g_w2rl[8192];

// ---------------- helpers ----------------
__device__ __forceinline__ uint32_t smem_u32(const void* p) {
    uint32_t a;
    asm("{ .reg .u64 t; cvta.to.shared.u64 t, %1; cvt.u32.u64 %0, t; }" : "=r"(a) : "l"(p));
    return a;
}
__device__ __forceinline__ void ldsm_x4(uint32_t& r0, uint32_t& r1, uint32_t& r2, uint32_t& r3,
                                        uint32_t addr) {
    asm volatile("ldmatrix.sync.aligned.m8n8.x4.shared.b16 {%0,%1,%2,%3}, [%4];"
                 : "=r"(r0), "=r"(r1), "=r"(r2), "=r"(r3) : "r"(addr));
}
__device__ __forceinline__ void mma16816(float* c, const uint32_t* a, const uint32_t* b) {
    asm volatile(
        "mma.sync.aligned.m16n8k16.row.col.f32.bf16.bf16.f32 "
        "{%0,%1,%2,%3}, {%4,%5,%6,%7}, {%8,%9}, {%0,%1,%2,%3};"
        : "+f"(c[0]), "+f"(c[1]), "+f"(c[2]), "+f"(c[3])
        : "r"(a[0]), "r"(a[1]), "r"(a[2]), "r"(a[3]), "r"(b[0]), "r"(b[1]));
}
__device__ __forceinline__ uint32_t pack2(float a, float b) {
    __nv_bfloat162 t = __floats2bfloat162_rn(a, b);
    return *(uint32_t*)&t;
}
__device__ __forceinline__ float4 h4_to_f4(uint2 u) {
    float2 a = __half22float2(*(__half2*)&u.x);
    float2 b = __half22float2(*(__half2*)&u.y);
    return make_float4(a.x, a.y, b.x, b.y);
}
__device__ __forceinline__ float lrelu(float v) { return v > 0.f ? v : 0.2f * v; }
__device__ __forceinline__ int edge_dst(const int* __restrict__ ei, int e, int E, int is64) {
    return is64 ? ei[2 * (E + e)] : ei[E + e];
}
__device__ __forceinline__ int edge_src(const int* __restrict__ ei, int e, int E, int is64) {
    return is64 ? ei[2 * e] : ei[e];
}

// ---------------- init: zero counts + dtype detect (block 0) ----------------
__global__ void k_init(const int* __restrict__ ei, int E, int N) {
    int t = blockIdx.x * blockDim.x + threadIdx.x;
    if (t < N) g_cnt[t] = 0;
    if (blockIdx.x == 0) {
        __shared__ int nz;
        if (threadIdx.x == 0) nz = 0;
        __syncthreads();
        int cnt = E < 4096 ? E : 4096;
        for (int i = threadIdx.x; i < cnt; i += blockDim.x)
            if (ei[2 * i + 1] != 0) nz = 1;
        __syncthreads();
        if (threadIdx.x == 0) g_is64 = (nz == 0) ? 1 : 0;
    }
}

// ---------------- CSR build ----------------
__global__ void k_hist(const int* __restrict__ ei, int E) {
    int e = blockIdx.x * blockDim.x + threadIdx.x;
    if (e >= E) return;
    atomicAdd(&g_cnt[edge_dst(ei, e, E, g_is64)], 1);
}
__global__ void k_scan1(int N) {
    __shared__ int wsum[32];
    const int tid = threadIdx.x;
    const int i = blockIdx.x * SCAN_B + tid;
    const int lane = tid & 31, wid = tid >> 5;
    int v = (i < N) ? g_cnt[i] : 0;
    int incl = v;
#pragma unroll
    for (int o = 1; o < 32; o <<= 1) {
        int t = __shfl_up_sync(0xFFFFFFFFu, incl, o);
        if (lane >= o) incl += t;
    }
    if (lane == 31) wsum[wid] = incl;
    __syncthreads();
    if (wid == 0) {
        int w = wsum[lane];
        int wi = w;
#pragma unroll
        for (int o = 1; o < 32; o <<= 1) {
            int t = __shfl_up_sync(0xFFFFFFFFu, wi, o);
            if (lane >= o) wi += t;
        }
        wsum[lane] = wi - w;
        if (lane == 31) g_bsum[blockIdx.x] = wi;
    }
    __syncthreads();
    if (i < N) g_off[i] = incl - v + wsum[wid];
}
__global__ void k_scan2(int NB, int N) {
    const int lane = threadIdx.x & 31, wid = threadIdx.x >> 5;
    __shared__ int wsum[4];
    int v = (threadIdx.x < NB) ? g_bsum[threadIdx.x] : 0;
    int incl = v;
#pragma unroll
    for (int o = 1; o < 32; o <<= 1) {
        int t = __shfl_up_sync(0xFFFFFFFFu, incl, o);
        if (lane >= o) incl += t;
    }
    if (lane == 31) wsum[wid] = incl;
    __syncthreads();
    int pre = 0;
    for (int w = 0; w < wid; w++) pre += wsum[w];
    if (threadIdx.x < NB) g_bpre[threadIdx.x] = pre + incl - v;
    if (threadIdx.x == 127) g_off[N] = pre + incl;
}
__global__ void k_scan3(int N) {
    int t = blockIdx.x * blockDim.x + threadIdx.x;
    if (t >= N) return;
    int o = g_off[t] + g_bpre[t >> 10];
    g_off[t] = o;
    g_cur[t] = o;
}
__global__ void k_scatter(const int* __restrict__ ei, int E) {
    int e = blockIdx.x * blockDim.x + threadIdx.x;
    if (e >= E) return;
    int is64 = g_is64;
    int s = edge_src(ei, e, E, is64), d = edge_dst(ei, e, E, is64);
    int pos = atomicAdd(&g_cur[d], 1);
    g_ssrc[pos] = s;
}

// ---------------- weight prep: transpose + bf16 split ----------------
__global__ void k_wprep(const float* __restrict__ W1l, const float* __restrict__ W1r,
                        const float* __restrict__ W2l, const float* __restrict__ W2r) {
    int t = blockIdx.x * blockDim.x + threadIdx.x;
    const float* W; __nv_bfloat16 *oh, *ol; int NOUT, idx;
    if      (t < 16384)  { W = W1l; oh = g_w1lh; ol = g_w1ll; NOUT = 128; idx = t; }
    else if (t < 32768)  { W = W1r; oh = g_w1rh; ol = g_w1rl; NOUT = 128; idx = t - 16384; }
    else if (t < 40960)  { W = W2l; oh = g_w2lh; ol = g_w2ll; NOUT = 64;  idx = t - 32768; }
    else if (t < 49152)  { W = W2r; oh = g_w2rh; ol = g_w2rl; NOUT = 64;  idx = t - 40960; }
    else return;
    int n = idx >> 7, k = idx & 127;
    float v = W[k * NOUT + n];
    __nv_bfloat16 h = __float2bfloat16_rn(v);
    oh[idx] = h;
    ol[idx] = __float2bfloat16_rn(v - __bfloat162float(h));
}

// ---------------- mma.sync GEMM pair ----------------
template <int NOUT>
__global__ void __launch_bounds__(256, 1) k_gemm_mma(
    const float* __restrict__ X,
    const __nv_bfloat16* __restrict__ Wlh, const __nv_bfloat16* __restrict__ Wll,
    const __nv_bfloat16* __restrict__ Wrh, const __nv_bfloat16* __restrict__ Wrl,
    const float* __restrict__ bl, const float* __restrict__ br,
    __half* __restrict__ Ylh, float* __restrict__ Yr, int nrows)
{
    constexpr int PITCH = 136;
    constexpr int ABYTES = 128 * PITCH * 2;
    constexpr int BBYTES = NOUT * PITCH * 2;
    constexpr int NFRAG = NOUT / 16;
    constexpr int WN = NOUT / 2;

    extern __shared__ char sm[];
    __nv_bfloat16* Ah = (__nv_bfloat16*)sm;
    __nv_bfloat16* Al = (__nv_bfloat16*)(sm + ABYTES);
    __nv_bfloat16* Bt = (__nv_bfloat16*)(sm + 2 * ABYTES);

    const int tid = threadIdx.x, wid = tid >> 5, lane = tid & 31;
    const int wm = wid & 3, wn = wid >> 2;
    const int base = blockIdx.x * 128;

    for (int c = tid; c < 2048; c += 256) {
        int row = c >> 4, col8 = (c & 15) << 3;
        int gr = base + row;
        float4 v0 = make_float4(0.f, 0.f, 0.f, 0.f), v1 = v0;
        if (gr < nrows) {
            v0 = *(const float4*)&X[(size_t)gr * 128 + col8];
            v1 = *(const float4*)&X[(size_t)gr * 128 + col8 + 4];
        }
        float in[8] = {v0.x, v0.y, v0.z, v0.w, v1.x, v1.y, v1.z, v1.w};
        float hf[8], lf[8];
#pragma unroll
        for (int i = 0; i < 8; i++) {
            __nv_bfloat16 hb = __float2bfloat16_rn(in[i]);
            hf[i] = __bfloat162float(hb);
            lf[i] = in[i] - hf[i];
        }
        uint4 hh = make_uint4(pack2(hf[0], hf[1]), pack2(hf[2], hf[3]),
                              pack2(hf[4], hf[5]), pack2(hf[6], hf[7]));
        uint4 ll = make_uint4(pack2(lf[0], lf[1]), pack2(lf[2], lf[3]),
                              pack2(lf[4], lf[5]), pack2(lf[6], lf[7]));
        *(uint4*)&Ah[row * PITCH + col8] = hh;
        *(uint4*)&Al[row * PITCH + col8] = ll;
    }
    const __nv_bfloat16* wsrc[4] = {Wlh, Wll, Wrh, Wrl};
#pragma unroll
    for (int w = 0; w < 4; w++) {
        __nv_bfloat16* dst = Bt + w * (NOUT * PITCH);
        const __nv_bfloat16* src = wsrc[w];
        for (int c = tid; c < NOUT * 16; c += 256) {
            int row = c >> 4, col8 = (c & 15) << 3;
            *(uint4*)&dst[row * PITCH + col8] = *(const uint4*)&src[row * 128 + col8];
        }
    }
    __syncthreads();

    const int quad = lane >> 3, r = lane & 7;
    const int a_row_off = (quad & 1) * 8 + r, a_col_off = (quad >> 1) * 8;
    const int b_row_off = (quad >> 1) * 8 + r, b_col_off = (quad & 1) * 8;

    const uint32_t ah_u = smem_u32(Ah), al_u = smem_u32(Al), b_u = smem_u32(Bt);

#pragma unroll
    for (int out = 0; out < 2; out++) {
        float acc[2][NFRAG][4];
#pragma unroll
        for (int mf = 0; mf < 2; mf++)
#pragma unroll
            for (int nf = 0; nf < NFRAG; nf++)
                acc[mf][nf][0] = acc[mf][nf][1] = acc[mf][nf][2] = acc[mf][nf][3] = 0.f;

#pragma unroll
        for (int p = 0; p < 3; p++) {
            uint32_t a_base = (p == 2) ? al_u : ah_u;
            uint32_t b_base = b_u + (uint32_t)(out * 2 + (p == 1)) * BBYTES;
#pragma unroll
            for (int ks = 0; ks < 8; ks++) {
                uint32_t af[2][4];
#pragma unroll
                for (int mf = 0; mf < 2; mf++) {
                    uint32_t ad = a_base +
                        ((wm * 32 + mf * 16 + a_row_off) * PITCH + ks * 16 + a_col_off) * 2;
                    ldsm_x4(af[mf][0], af[mf][1], af[mf][2], af[mf][3], ad);
                }
                uint32_t bfr[NFRAG][2];
#pragma unroll
                for (int nfp = 0; nfp < NFRAG / 2; nfp++) {
                    uint32_t bd = b_base +
                        ((wn * WN + nfp * 16 + b_row_off) * PITCH + ks * 16 + b_col_off) * 2;
                    uint32_t d0, d1, d2, d3;
                    ldsm_x4(d0, d1, d2, d3, bd);
                    bfr[2 * nfp][0] = d0; bfr[2 * nfp][1] = d1;
                    bfr[2 * nfp + 1][0] = d2; bfr[2 * nfp + 1][1] = d3;
                }
#pragma unroll
                for (int mf = 0; mf < 2; mf++)
#pragma unroll
                    for (int nf = 0; nf < NFRAG; nf++)
                        mma16816(acc[mf][nf], af[mf], bfr[nf]);
            }
        }

        const float* bias = out ? br : bl;
#pragma unroll
        for (int mf = 0; mf < 2; mf++) {
            int row0 = base + wm * 32 + mf * 16 + (lane >> 2);
#pragma unroll
            for (int nf = 0; nf < NFRAG; nf++) {
                int col = wn * WN + nf * 8 + (lane & 3) * 2;
                float b0 = __ldg(&bias[col]), b1 = __ldg(&bias[col + 1]);
                if (out == 0) {
                    if (row0 < nrows)
                        *(__half2*)&Ylh[(size_t)row0 * NOUT + col] =
                            __floats2half2_rn(acc[mf][nf][0] + b0, acc[mf][nf][1] + b1);
                    if (row0 + 8 < nrows)
                        *(__half2*)&Ylh[(size_t)(row0 + 8) * NOUT + col] =
                            __floats2half2_rn(acc[mf][nf][2] + b0, acc[mf][nf][3] + b1);
                } else {
                    if (row0 < nrows)
                        *(float2*)&Yr[(size_t)row0 * NOUT + col] =
                            make_float2(acc[mf][nf][0] + b0, acc[mf][nf][1] + b1);
                    if (row0 + 8 < nrows)
                        *(float2*)&Yr[(size_t)(row0 + 8) * NOUT + col] =
                            make_float2(acc[mf][nf][2] + b0, acc[mf][nf][3] + b1);
                }
            }
        }
    }
}

// ---------------- layer 1 attention: 2-edge unrolled online softmax ----------------
__global__ void k_attn1(const float* __restrict__ att, const float* __restrict__ bias, int N) {
    int node = blockIdx.x * 8 + (threadIdx.x >> 5);
    int lane = threadIdx.x & 31;
    if (node >= N) return;
    const int d = node;
    const __half* XL = g_xl1h;

    float4 xr = *(const float4*)&g_xr1[(size_t)d * 128 + lane * 4];
    float4 at = *(const float4*)&att[lane * 4];

    float4 self = h4_to_f4(*(const uint2*)&XL[(size_t)d * 128 + lane * 4]);
    float sc = lrelu(self.x + xr.x) * at.x + lrelu(self.y + xr.y) * at.y +
               lrelu(self.z + xr.z) * at.z + lrelu(self.w + xr.w) * at.w;
    sc += __shfl_xor_sync(0xFFFFFFFFu, sc, 1);
    sc += __shfl_xor_sync(0xFFFFFFFFu, sc, 2);
    float m = sc, den = 1.f;
    float4 acc = self;

    const int beg = g_off[d];
    const int cnt = g_off[d + 1] - beg;
    uint2 va, vb;
    if (cnt > 0) {
        int s0 = __ldg(&g_ssrc[beg]);
        va = *(const uint2*)&XL[(size_t)s0 * 128 + lane * 4];
    }
    if (cnt > 1) {
        int s1 = __ldg(&g_ssrc[beg + 1]);
        vb = *(const uint2*)&XL[(size_t)s1 * 128 + lane * 4];
    }
    int j = 0;
    for (; j + 1 < cnt; j += 2) {
        float4 c0 = h4_to_f4(va), c1 = h4_to_f4(vb);
        if (j + 2 < cnt) {
            int sn = __ldg(&g_ssrc[beg + j + 2]);
            va = *(const uint2*)&XL[(size_t)sn * 128 + lane * 4];
        }
        if (j + 3 < cnt) {
            int sn = __ldg(&g_ssrc[beg + j + 3]);
            vb = *(const uint2*)&XL[(size_t)sn * 128 + lane * 4];
        }
        float s0 = lrelu(c0.x + xr.x) * at.x + lrelu(c0.y + xr.y) * at.y +
                   lrelu(c0.z + xr.z) * at.z + lrelu(c0.w + xr.w) * at.w;
        float s1 = lrelu(c1.x + xr.x) * at.x + lrelu(c1.y + xr.y) * at.y +
                   lrelu(c1.z + xr.z) * at.z + lrelu(c1.w + xr.w) * at.w;
        s0 += __shfl_xor_sync(0xFFFFFFFFu, s0, 1);
        s1 += __shfl_xor_sync(0xFFFFFFFFu, s1, 1);
        s0 += __shfl_xor_sync(0xFFFFFFFFu, s0, 2);
        s1 += __shfl_xor_sync(0xFFFFFFFFu, s1, 2);
        float nm = fmaxf(m, fmaxf(s0, s1));
        float cold = __expf(m - nm), w0 = __expf(s0 - nm), w1 = __expf(s1 - nm);
        den = den * cold + w0 + w1;
        acc.x = acc.x * cold + w0 * c0.x + w1 * c1.x;
        acc.y = acc.y * cold + w0 * c0.y + w1 * c1.y;
        acc.z = acc.z * cold + w0 * c0.z + w1 * c1.z;
        acc.w = acc.w * cold + w0 * c0.w + w1 * c1.w;
        m = nm;
    }
    if (j < cnt) {   // odd leftover (in va)
        float4 c0 = h4_to_f4(va);
        float s0 = lrelu(c0.x + xr.x) * at.x + lrelu(c0.y + xr.y) * at.y +
                   lrelu(c0.z + xr.z) * at.z + lrelu(c0.w + xr.w) * at.w;
        s0 += __shfl_xor_sync(0xFFFFFFFFu, s0, 1);
        s0 += __shfl_xor_sync(0xFFFFFFFFu, s0, 2);
        float nm = fmaxf(m, s0);
        float cold = __expf(m - nm), w0 = __expf(s0 - nm);
        den = den * cold + w0;
        acc.x = acc.x * cold + w0 * c0.x;
        acc.y = acc.y * cold + w0 * c0.y;
        acc.z = acc.z * cold + w0 * c0.z;
        acc.w = acc.w * cold + w0 * c0.w;
        m = nm;
    }
    float inv = 1.f / den;
    float4 bi = *(const float4*)&bias[lane * 4];
    float4 o;
    o.x = acc.x * inv + bi.x; o.y = acc.y * inv + bi.y;
    o.z = acc.z * inv + bi.z; o.w = acc.w * inv + bi.w;
    o.x = o.x > 0.f ? o.x : expm1f(o.x);
    o.y = o.y > 0.f ? o.y : expm1f(o.y);
    o.z = o.z > 0.f ? o.z : expm1f(o.z);
    o.w = o.w > 0.f ? o.w : expm1f(o.w);
    *(float4*)&g_h[(size_t)d * 128 + lane * 4] = o;
}

// ---------------- layer 2 attention: 2-edge unrolled ----------------
__global__ void k_attn2(const float* __restrict__ att2, const float* __restrict__ bias2,
                        float* __restrict__ dout, int N) {
    int node = blockIdx.x * 8 + (threadIdx.x >> 5);
    int lane = threadIdx.x & 31;
    if (node >= N) return;
    const int d = node;
    const __half* XL = g_xl2h;

    float2 xr = *(const float2*)&g_xr2[(size_t)d * 64 + lane * 2];
    float2 at = *(const float2*)&att2[lane * 2];

    float2 self = __half22float2(*(const __half2*)&XL[(size_t)d * 64 + lane * 2]);
    float sc = lrelu(self.x + xr.x) * at.x + lrelu(self.y + xr.y) * at.y;
#pragma unroll
    for (int o = 16; o; o >>= 1) sc += __shfl_xor_sync(0xFFFFFFFFu, sc, o);
    float m = sc, den = 1.f;
    float acc0 = self.x, acc1 = self.y;

    const int beg = g_off[d];
    const int cnt = g_off[d + 1] - beg;
    uint32_t va, vb;
    if (cnt > 0) {
        int s0 = __ldg(&g_ssrc[beg]);
        va = *(const uint32_t*)&XL[(size_t)s0 * 64 + lane * 2];
    }
    if (cnt > 1) {
        int s1 = __ldg(&g_ssrc[beg + 1]);
        vb = *(const uint32_t*)&XL[(size_t)s1 * 64 + lane * 2];
    }
    int j = 0;
    for (; j + 1 < cnt; j += 2) {
        float2 c0 = __half22float2(*(__half2*)&va);
        float2 c1 = __half22float2(*(__half2*)&vb);
        if (j + 2 < cnt) {
            int sn = __ldg(&g_ssrc[beg + j + 2]);
            va = *(const uint32_t*)&XL[(size_t)sn * 64 + lane * 2];
        }
        if (j + 3 < cnt) {
            int sn = __ldg(&g_ssrc[beg + j + 3]);
            vb = *(const uint32_t*)&XL[(size_t)sn * 64 + lane * 2];
        }
        float s0 = lrelu(c0.x + xr.x) * at.x + lrelu(c0.y + xr.y) * at.y;
        float s1 = lrelu(c1.x + xr.x) * at.x + lrelu(c1.y + xr.y) * at.y;
#pragma unroll
        for (int o = 16; o; o >>= 1) {
            s0 += __shfl_xor_sync(0xFFFFFFFFu, s0, o);
            s1 += __shfl_xor_sync(0xFFFFFFFFu, s1, o);
        }
        float nm = fmaxf(m, fmaxf(s0, s1));
        float cold = __expf(m - nm), w0 = __expf(s0 - nm), w1 = __expf(s1 - nm);
        den = den * cold + w0 + w1;
        acc0 = acc0 * cold + w0 * c0.x + w1 * c1.x;
        acc1 = acc1 * cold + w0 * c0.y + w1 * c1.y;
        m = nm;
    }
    if (j < cnt) {
        float2 c0 = __half22float2(*(__half2*)&va);
        float s0 = lrelu(c0.x + xr.x) * at.x + lrelu(c0.y + xr.y) * at.y;
#pragma unroll
        for (int o = 16; o; o >>= 1) s0 += __shfl_xor_sync(0xFFFFFFFFu, s0, o);
        float nm = fmaxf(m, s0);
        float cold = __expf(m - nm), w0 = __expf(s0 - nm);
        den = den * cold + w0;
        acc0 = acc0 * cold + w0 * c0.x;
        acc1 = acc1 * cold + w0 * c0.y;
        m = nm;
    }
    float inv = 1.f / den;
    float2 bi = *(const float2*)&bias2[lane * 2];
    *(float2*)&dout[(size_t)d * 64 + lane * 2] =
        make_float2(acc0 * inv + bi.x, acc1 * inv + bi.y);
}

// ---------------- launch ----------------
static inline int cdiv(long long a, int b) { return (int)((a + b - 1) / b); }

extern "C" void kernel_launch(void* const* d_in, const int* in_sizes, int n_in,
                              void* d_out, int out_size) {
    const float* x    = (const float*)d_in[0];
    const int*   ei   = (const int*)d_in[1];
    const float* Wl1  = (const float*)d_in[2];
    const float* bl1  = (const float*)d_in[3];
    const float* Wr1  = (const float*)d_in[4];
    const float* br1  = (const float*)d_in[5];
    const float* att1 = (const float*)d_in[6];
    const float* bias1= (const float*)d_in[7];
    const float* Wl2  = (const float*)d_in[8];
    const float* bl2  = (const float*)d_in[9];
    const float* Wr2  = (const float*)d_in[10];
    const float* br2  = (const float*)d_in[11];
    const float* att2 = (const float*)d_in[12];
    const float* bias2= (const float*)d_in[13];
    float* dout = (float*)d_out;

    const int N = in_sizes[0] / 128;
    const int E = in_sizes[1] / 2;
    const int NB = cdiv(N, SCAN_B);

    float *xr1, *h, *xr2;
    __half *xl1h, *xl2h;
    cudaGetSymbolAddress((void**)&xl1h, g_xl1h);
    cudaGetSymbolAddress((void**)&xr1,  g_xr1);
    cudaGetSymbolAddress((void**)&h,    g_h);
    cudaGetSymbolAddress((void**)&xl2h, g_xl2h);
    cudaGetSymbolAddress((void**)&xr2,  g_xr2);
    __nv_bfloat16 *w1lh, *w1ll, *w1rh, *w1rl, *w2lh, *w2ll, *w2rh, *w2rl;
    cudaGetSymbolAddress((void**)&w1lh, g_w1lh);
    cudaGetSymbolAddress((void**)&w1ll, g_w1ll);
    cudaGetSymbolAddress((void**)&w1rh, g_w1rh);
    cudaGetSymbolAddress((void**)&w1rl, g_w1rl);
    cudaGetSymbolAddress((void**)&w2lh, g_w2lh);
    cudaGetSymbolAddress((void**)&w2ll, g_w2ll);
    cudaGetSymbolAddress((void**)&w2rh, g_w2rh);
    cudaGetSymbolAddress((void**)&w2rl, g_w2rl);

    const int smem1 = 2 * 34816 + 4 * 34816;
    const int smem2 = 2 * 34816 + 4 * 17408;
    cudaFuncSetAttribute(k_gemm_mma<128>, cudaFuncAttributeMaxDynamicSharedMemorySize, smem1);
    cudaFuncSetAttribute(k_gemm_mma<64>,  cudaFuncAttributeMaxDynamicSharedMemorySize, smem2);

    // one-time side stream + fork/join events (host objects; deterministic reuse)
    static cudaStream_t s1 = nullptr;
    static cudaEvent_t evFork = nullptr, evJoin = nullptr;
    if (!s1) {
        cudaStreamCreateWithFlags(&s1, cudaStreamNonBlocking);
        cudaEventCreateWithFlags(&evFork, cudaEventDisableTiming);
        cudaEventCreateWithFlags(&evJoin, cudaEventDisableTiming);
    }

    // fork: side stream runs weight prep + layer-1 GEMM concurrently with CSR build
    cudaEventRecord(evFork, 0);
    cudaStreamWaitEvent(s1, evFork, 0);

    k_wprep<<<cdiv(49152, 256), 256, 0, s1>>>(Wl1, Wr1, Wl2, Wr2);
    k_gemm_mma<128><<<cdiv(N, 128), 256, smem1, s1>>>(x, w1lh, w1ll, w1rh, w1rl,
                                                      bl1, br1, xl1h, xr1, N);
    cudaEventRecord(evJoin, s1);

    // main stream: CSR build
    k_init   <<<cdiv(N, 256), 256>>>(ei, E, N);
    k_hist   <<<cdiv(E, 256), 256>>>(ei, E);
    k_scan1  <<<NB, SCAN_B>>>(N);
    k_scan2  <<<1, 128>>>(NB, N);
    k_scan3  <<<cdiv(N, 256), 256>>>(N);
    k_scatter<<<cdiv(E, 256), 256>>>(ei, E);

    // join: attention needs both CSR and GEMM1
    cudaStreamWaitEvent(0, evJoin, 0);

    k_attn1<<<cdiv(N, 8), 256>>>(att1, bias1, N);
    k_gemm_mma<64><<<cdiv(N, 128), 256, smem2>>>(h, w2lh, w2ll, w2rh, w2rl,
                                                 bl2, br2, xl2h, xr2, N);
    k_attn2<<<cdiv(N, 8), 256>>>(att2, bias2, dout, N);
}